// round 7
// baseline (speedup 1.0000x reference)
#include <cuda_runtime.h>
#include <cuda_fp16.h>
#include <math.h>
#include <stdint.h>

#define BZ 2
#define CC 128
#define NN 2304
#define WIMG 48
#define MC 256          // m-chunk width
#define NCH 9           // 2304 / 256
#define BPAD 68         // u32 row stride for staged A/B (68 mod 32 == 4 -> frag reads conflict-free)
#define SSTR 257        // Ss row stride (floats), 257 mod 32 == 1 -> column reads conflict-free

// ---------------- scratch (no allocations allowed) ----------------
__device__ __half g_Qh[BZ * NN * CC];            // img1 transposed -> [b][n][c] half
__device__ __half g_Th[BZ * NN * CC];            // img2 transposed -> [b][p][c] half
__device__ __half g_Dh[BZ * NN * CC];            // grid-sampled db  [b][n][c] half
__device__ float g_part[144];
__device__ unsigned g_ctr = 0;

// ---------------- kernel 1: transpose [b][c][p] -> [b][p][c] + cvt to half ----------
__global__ void k_prep(const float* __restrict__ img1, const float* __restrict__ img2) {
    __shared__ float tile[32][33];
    int img = blockIdx.z & 1;
    int b   = blockIdx.z >> 1;
    const float* in = (img == 0 ? img1 : img2) + (size_t)b * CC * NN;
    __half* out     = (img == 0 ? g_Qh : g_Th) + (size_t)b * NN * CC;

    int p0 = blockIdx.x * 32;
    int c0 = blockIdx.y * 32;
    int tx = threadIdx.x, ty = threadIdx.y;

#pragma unroll
    for (int j = 0; j < 4; j++)
        tile[ty + j * 8][tx] = in[(size_t)(c0 + ty + j * 8) * NN + p0 + tx];
    __syncthreads();
#pragma unroll
    for (int j = 0; j < 4; j++)
        out[(size_t)(p0 + ty + j * 8) * CC + c0 + tx] =
            __float2half(tile[tx][ty + j * 8]);
}

// ---------------- kernel 2: grid_sample, warp-per-point, coalesced ----------------
__global__ void k_gridsample(const float* __restrict__ grid) {
    int w    = threadIdx.x >> 5;
    int lane = threadIdx.x & 31;
    int n = blockIdx.x * 8 + w;
    int b = blockIdx.y;

    float gx = grid[((size_t)b * NN + n) * 2 + 0];
    float gy = grid[((size_t)b * NN + n) * 2 + 1];
    float ix = fmaf(gx, 24.0f, 23.5f);
    float iy = fmaf(gy, 24.0f, 23.5f);
    float x0f = floorf(ix), y0f = floorf(iy);
    float wx = ix - x0f, wy = iy - y0f;
    int x0 = (int)x0f, y0 = (int)y0f;
    int x1 = x0 + 1,  y1 = y0 + 1;

    bool vx0 = (x0 >= 0) & (x0 < WIMG);
    bool vx1 = (x1 >= 0) & (x1 < WIMG);
    bool vy0 = (y0 >= 0) & (y0 < WIMG);
    bool vy1 = (y1 >= 0) & (y1 < WIMG);

    float w00 = (vx0 & vy0) ? (1.f - wx) * (1.f - wy) : 0.f;
    float w10 = (vx1 & vy0) ? wx * (1.f - wy)         : 0.f;
    float w01 = (vx0 & vy1) ? (1.f - wx) * wy         : 0.f;
    float w11 = (vx1 & vy1) ? wx * wy                 : 0.f;

    int cx0 = min(max(x0, 0), WIMG - 1), cx1 = min(max(x1, 0), WIMG - 1);
    int cy0 = min(max(y0, 0), WIMG - 1), cy1 = min(max(y1, 0), WIMG - 1);

    const __half* T = g_Th + (size_t)b * NN * CC;
    int p00 = cy0 * WIMG + cx0, p10 = cy0 * WIMG + cx1;
    int p01 = cy1 * WIMG + cx0, p11 = cy1 * WIMG + cx1;

    uint2 v00 = ((const uint2*)(T + (size_t)p00 * CC))[lane];
    uint2 v10 = ((const uint2*)(T + (size_t)p10 * CC))[lane];
    uint2 v01 = ((const uint2*)(T + (size_t)p01 * CC))[lane];
    uint2 v11 = ((const uint2*)(T + (size_t)p11 * CC))[lane];

    float r[4];
#pragma unroll
    for (int h = 0; h < 2; h++) {
        float2 f00 = __half22float2(((__half2*)&v00)[h]);
        float2 f10 = __half22float2(((__half2*)&v10)[h]);
        float2 f01 = __half22float2(((__half2*)&v01)[h]);
        float2 f11 = __half22float2(((__half2*)&v11)[h]);
        r[2 * h + 0] = w00 * f00.x + w10 * f10.x + w01 * f01.x + w11 * f11.x;
        r[2 * h + 1] = w00 * f00.y + w10 * f10.y + w01 * f01.y + w11 * f11.y;
    }
    uint2 o;
    ((__half2*)&o)[0] = __floats2half2_rn(r[0], r[1]);
    ((__half2*)&o)[1] = __floats2half2_rn(r[2], r[3]);
    ((uint2*)(g_Dh + ((size_t)b * NN + n) * CC))[lane] = o;
}

// ---------------- fp16 MMA helper ----------------
__device__ __forceinline__ void mma_f16(float* d, const uint32_t* a, const uint32_t* bb) {
    asm volatile(
        "mma.sync.aligned.m16n8k16.row.col.f32.f16.f16.f32 "
        "{%0,%1,%2,%3}, {%4,%5,%6,%7}, {%8,%9}, {%0,%1,%2,%3};"
        : "+f"(d[0]), "+f"(d[1]), "+f"(d[2]), "+f"(d[3])
        : "r"(a[0]), "r"(a[1]), "r"(a[2]), "r"(a[3]), "r"(bb[0]), "r"(bb[1]));
}

// ---------------- kernel 3: per-n-tile GEMM + binning + AP/loss, fully fused ----
// block = (nt 0..71, b). Tile: 32 n-rows; loops 9 chunks of 256 m. 256 threads, 1 block/SM.
#define SM_SS   0                          // 32*257   = 8224 (also reused as Hred 32*51)
#define SM_HN   (SM_SS + 32 * SSTR)        // 26*256   = 6656
#define SM_HR   (SM_HN + 26 * 256)         // 6656
#define SM_RC   (SM_HR + 26 * 256)         // 256 ints
#define SM_A    (SM_RC + 256)              // 32*68 u32  = 2176
#define SM_B    (SM_A + 32 * BPAD)         // 256*68 u32 = 17408
#define SM_TOT  (SM_B + 256 * BPAD)        // 41376 floats = 165.5 KB

__global__ void __launch_bounds__(256, 1) k_main(const float* __restrict__ rel,
                                                 float* __restrict__ out) {
    extern __shared__ float smf[];
    float*    Ss  = smf + SM_SS;
    float*    hN  = smf + SM_HN;
    float*    hR  = smf + SM_HR;
    int*      rcM = (int*)(smf + SM_RC);
    uint32_t* As2 = (uint32_t*)(smf + SM_A);
    uint32_t* Bs2 = (uint32_t*)(smf + SM_B);

    const int t  = threadIdx.x;
    const int w  = t >> 5;
    const int ln = t & 31;
    const int g  = ln >> 2;
    const int tg = ln & 3;
    const int nt = blockIdx.x;
    const int b  = blockIdx.y;
    const int n0 = nt * 32;

    // zero private hist columns
#pragma unroll
    for (int c = 0; c < 26; c++) { hN[c * 256 + t] = 0.f; hR[c * 256 + t] = 0.f; }

    // stage A (32 queries x 128 c) once: 512 uint4, 2 per thread
    const __half* Qh = g_Qh + ((size_t)b * NN + n0) * CC;
#pragma unroll
    for (int i = 0; i < 2; i++) {
        int idx = t + i * 256;
        int row = idx >> 4, c4 = idx & 15;
        uint4 v = ((const uint4*)(Qh + (size_t)row * CC))[c4];
        *(uint4*)&As2[row * BPAD + c4 * 4] = v;
    }

    const int ng = n0 + ln;
    const int rn = ng / WIMG;
    const int cn = ng - rn * WIMG;

    const __half* Dh = g_Dh + (size_t)b * NN * CC;

    for (int mc = 0; mc < NCH; mc++) {
        const int m0 = mc * MC;
#pragma unroll
        for (int i = 0; i < 16; i++) {
            int idx = t + i * 256;
            int m = idx >> 4, c4 = idx & 15;
            uint4 v = ((const uint4*)(Dh + (size_t)(m0 + m) * CC))[c4];
            *(uint4*)&Bs2[m * BPAD + c4 * 4] = v;
        }
        {
            int mg = m0 + t;
            int rm = mg / WIMG;
            rcM[t] = (rm << 8) | (mg - rm * WIMG);
        }
        __syncthreads();

        // ---- GEMM: warp w covers all 32 rows x cols [w*32, w*32+32) ----
        float acc[2][4][4];
#pragma unroll
        for (int i = 0; i < 2; i++)
#pragma unroll
            for (int j = 0; j < 4; j++)
#pragma unroll
                for (int k = 0; k < 4; k++) acc[i][j][k] = 0.f;

#pragma unroll
        for (int kk = 0; kk < 8; kk++) {
            int kb = kk * 8 + tg;
            uint32_t af[2][4];
#pragma unroll
            for (int rt = 0; rt < 2; rt++) {
                int nb = rt * 16 + g;
                af[rt][0] = As2[nb * BPAD + kb];
                af[rt][1] = As2[(nb + 8) * BPAD + kb];
                af[rt][2] = As2[nb * BPAD + kb + 4];
                af[rt][3] = As2[(nb + 8) * BPAD + kb + 4];
            }
            uint32_t bf[4][2];
#pragma unroll
            for (int ct = 0; ct < 4; ct++) {
                int mb = w * 32 + ct * 8 + g;
                bf[ct][0] = Bs2[mb * BPAD + kb];
                bf[ct][1] = Bs2[mb * BPAD + kb + 4];
            }
#pragma unroll
            for (int rt = 0; rt < 2; rt++)
#pragma unroll
                for (int ct = 0; ct < 4; ct++)
                    mma_f16(acc[rt][ct], af[rt], bf[ct]);
        }

        // ---- fragments -> Ss ----
#pragma unroll
        for (int rt = 0; rt < 2; rt++) {
            int row = rt * 16 + g;
#pragma unroll
            for (int ct = 0; ct < 4; ct++) {
                int col = w * 32 + ct * 8 + tg * 2;
                Ss[row * SSTR + col]           = acc[rt][ct][0];
                Ss[row * SSTR + col + 1]       = acc[rt][ct][1];
                Ss[(row + 8) * SSTR + col]     = acc[rt][ct][2];
                Ss[(row + 8) * SSTR + col + 1] = acc[rt][ct][3];
            }
        }
        __syncthreads();

        // ---- binning: lane = row, warp w covers m-slice [w*32, w*32+32) ----
        {
            float* hNc = hN + t;
            float* hRc = hR + t;
#pragma unroll 4
            for (int m = 0; m < 32; m++) {
                int ml = w * 32 + m;
                float s = Ss[ln * SSTR + ml];
                int rcm = rcM[ml];
                int dr = (rcm >> 8) - rn;
                int dc = (rcm & 255) - cn;
                bool lab = (abs(dr) <= 4) && (abs(dc) <= 4);
                float tq = fmaf(s, -12.f, 12.f);
                tq = fminf(fmaxf(tq, 0.f), 24.f);
                float cf = floorf(tq);
                int c0 = (int)cf;
                float whi = tq - cf;
                float wlo = 1.f - whi;
                hNc[c0 * 256]       += wlo;
                hNc[c0 * 256 + 256] += whi;
                if (__any_sync(0xffffffffu, lab)) {
                    if (lab) {
                        hRc[c0 * 256]       += wlo;
                        hRc[c0 * 256 + 256] += whi;
                    }
                }
            }
        }
        __syncthreads();   // protect Bs2/rcM for next chunk
    }

    // ---- flush: reduce 8 warp-columns into Hred[r*51 + s] (reuses Ss) ----
    float* Hred = Ss;   // 32*51 = 1632 floats
#pragma unroll
    for (int kk = 0; kk < 7; kk++) {
        int idx = t + kk * 256;            // 0..1599 used
        if (idx < 1600) {
            int s50 = idx >> 5;            // 0..49
            int r   = idx & 31;
            float* hh = (s50 < 25) ? (hN + s50 * 256) : (hR + (s50 - 25) * 256);
            float v = 0.f;
#pragma unroll
            for (int w8 = 0; w8 < 8; w8++) v += hh[w8 * 32 + r];
            Hred[r * 51 + s50] = v;
        }
    }
    __syncthreads();

    // ---- epilogue: warp 0 computes AP + loss for its 32 rows ----
    if (t < 32) {
        const int r = t;
        float cumn = 0.f, cumr = 0.f, sap = 0.f, sr = 0.f;
#pragma unroll
        for (int c = 0; c < 25; c++) {
            float nb = Hred[r * 51 + c];
            float rv = Hred[r * 51 + 25 + c];
            cumn += nb;
            cumr += rv;
            float prec = cumr / (1e-16f + cumn);
            sap = fmaf(prec, rv, sap);
            sr += rv;
        }
        float ap = sap / sr;
        float rl = rel[(size_t)b * NN + n0 + r];
        float loss = 1.f - (ap * rl + 0.5f * (1.f - rl));
#pragma unroll
        for (int o = 16; o > 0; o >>= 1)
            loss += __shfl_down_sync(0xffffffffu, loss, o);
        if (r == 0) {
            g_part[b * 72 + nt] = loss;
            __threadfence();
            unsigned old = atomicAdd(&g_ctr, 1u);
            if (old == 143u) {
                __threadfence();
                float ssum = 0.f;
#pragma unroll
                for (int i = 0; i < 144; i++) ssum += g_part[i];
                out[0] = ssum * (1.0f / 4608.0f);
                g_ctr = 0u;
            }
        }
    }
}

// ---------------- launch ----------------
extern "C" void kernel_launch(void* const* d_in, const int* in_sizes, int n_in,
                              void* d_out, int out_size) {
    const float* img1 = (const float*)d_in[0];
    const float* img2 = (const float*)d_in[1];
    const float* rel  = (const float*)d_in[2];
    const float* grid = (const float*)d_in[3];

    cudaFuncSetAttribute(k_main, cudaFuncAttributeMaxDynamicSharedMemorySize,
                         SM_TOT * (int)sizeof(float));

    k_prep<<<dim3(72, 4, 4), dim3(32, 8)>>>(img1, img2);
    k_gridsample<<<dim3(288, 2), 256>>>(grid);
    k_main<<<dim3(72, 2), 256, SM_TOT * (int)sizeof(float)>>>(rel, (float*)d_out);
}